// round 4
// baseline (speedup 1.0000x reference)
#include <cuda_runtime.h>
#include <cuda_bf16.h>

#define NSEG 2048
#define EPS 1e-6f

__device__ __forceinline__ float dot4(float4 a, float4 b) {
    return a.x * b.x + a.y * b.y + a.z * b.z + a.w * b.w;
}
__device__ __forceinline__ float sum4(float4 a) {
    return a.x + a.y + a.z + a.w;
}

// Warp-parallel lower_bound over sorted batch: smallest i with batch[i] >= target.
// 32-ary search: ~4 ballot rounds for n=200000.
__device__ __forceinline__ int warp_lower_bound(const int* __restrict__ batch,
                                                int n, int target, int lane)
{
    int lo = -1, hi = n;   // invariant: batch[lo] < target <= batch[hi] (sentinels)
    while (hi - lo > 1) {
        int span = hi - lo - 1;                       // >= 1
        int pos  = lo + 1 + (int)(((long long)span * lane) >> 5);  // in [lo+1, hi-1]
        int val  = __ldg(batch + pos);
        unsigned ball = __ballot_sync(0xFFFFFFFFu, val >= target);
        if (ball == 0) {
            lo = lo + 1 + (int)(((long long)span * 31) >> 5);
        } else {
            int k0 = __ffs((int)ball) - 1;
            int hi_new = __shfl_sync(0xFFFFFFFFu, pos, k0);
            int lo_new = (k0 > 0) ? __shfl_sync(0xFFFFFFFFu, pos, k0 - 1) : lo;
            hi = hi_new;
            lo = lo_new;
        }
    }
    return hi;
}

// One CTA per segment (batch is sorted -> contiguous node range).
// Pass 1: stats (loads allocate in L2). Pass 2: normalize in REVERSE order
// (MRU-first), .cs loads / .cs stores, software-pipelined.
__global__ __launch_bounds__(512, 1) void fused_kernel(
    const float* __restrict__ s, const float* __restrict__ v,
    const float* __restrict__ weight, const float* __restrict__ bias,
    const int* __restrict__ batch, int n,
    float* __restrict__ sout, float* __restrict__ vout)
{
    __shared__ float sh_acc[3];
    __shared__ int   sh_n0, sh_n1;

    int seg  = blockIdx.x;
    int warp = threadIdx.x >> 5;    // 16 warps
    int lane = threadIdx.x & 31;

    if (threadIdx.x < 3) sh_acc[threadIdx.x] = 0.f;
    if (warp == 0) {
        int n0 = warp_lower_bound(batch, n, seg, lane);
        if (lane == 0) sh_n0 = n0;
    } else if (warp == 1) {
        int n1 = warp_lower_bound(batch, n, seg + 1, lane);
        if (lane == 0) sh_n1 = n1;
    }
    __syncthreads();

    int n0 = sh_n0;
    int n1 = sh_n1;
    int cnt = n1 - n0;
    if (cnt == 0) return;           // empty segment: nothing to write

    // ---- pass 1: stats (forward traversal) ----
    float sa = 0.f, sb = 0.f, sw = 0.f;
    for (int node = n0 + warp; node < n1; node += 16) {
        const float4* srow = (const float4*)(s + (size_t)node * 256);
        const float4* vrow = (const float4*)(v + (size_t)node * 384);
        float4 x0 = srow[lane];
        float4 x1 = srow[lane + 32];
        float4 y0 = vrow[lane];
        float4 y1 = vrow[lane + 32];
        float4 y2 = vrow[lane + 64];
        sa += sum4(x0) + sum4(x1);
        sb += dot4(x0, x0) + dot4(x1, x1);
        sw += dot4(y0, y0) + dot4(y1, y1) + dot4(y2, y2);
    }
    #pragma unroll
    for (int o = 16; o > 0; o >>= 1) {
        sa += __shfl_xor_sync(0xFFFFFFFFu, sa, o);
        sb += __shfl_xor_sync(0xFFFFFFFFu, sb, o);
        sw += __shfl_xor_sync(0xFFFFFFFFu, sw, o);
    }
    if (lane == 0) {
        atomicAdd(&sh_acc[0], sa);
        atomicAdd(&sh_acc[1], sb);
        atomicAdd(&sh_acc[2], sw);
    }

    // ---- prefetch first pass-2 tile (independent of stats) ----
    int node = n1 - 1 - warp;
    float4 x0, x1, y0, y1, y2;
    if (node >= n0) {
        const float4* srow = (const float4*)(s + (size_t)node * 256);
        const float4* vrow = (const float4*)(v + (size_t)node * 384);
        x0 = __ldcs(srow + lane);
        x1 = __ldcs(srow + lane + 32);
        y0 = __ldcs(vrow + lane);
        y1 = __ldcs(vrow + lane + 32);
        y2 = __ldcs(vrow + lane + 64);
    }
    float4 w0 = ((const float4*)weight)[lane];
    float4 w1 = ((const float4*)weight)[lane + 32];
    float4 b0 = ((const float4*)bias)[lane];
    float4 b1 = ((const float4*)bias)[lane + 32];

    __syncthreads();

    // stats: every thread computes redundantly (saves a barrier)
    float c   = (float)cnt;
    float sm  = sh_acc[0] * (1.f / 256.f) / c;
    float ex2 = sh_acc[1] * (1.f / 256.f) / c;
    float var = fmaxf(ex2 - sm * sm, EPS);
    float vm  = fmaxf(sh_acc[2] * (1.f / 128.f) / c, EPS);
    float iva = __fdividef(1.f, var);
    float ivm = __fdividef(1.f, vm);

    // ---- pass 2: normalize (reverse, software-pipelined) ----
    while (node >= n0) {
        int nxt = node - 16;
        float4 nx0, nx1, ny0, ny1, ny2;
        if (nxt >= n0) {
            const float4* srow = (const float4*)(s + (size_t)nxt * 256);
            const float4* vrow = (const float4*)(v + (size_t)nxt * 384);
            nx0 = __ldcs(srow + lane);
            nx1 = __ldcs(srow + lane + 32);
            ny0 = __ldcs(vrow + lane);
            ny1 = __ldcs(vrow + lane + 32);
            ny2 = __ldcs(vrow + lane + 64);
        }

        float4* so = (float4*)(sout + (size_t)node * 256);
        float4* vo = (float4*)(vout + (size_t)node * 384);

        float4 o0, o1;
        o0.x = (x0.x - sm) * iva * w0.x + b0.x;
        o0.y = (x0.y - sm) * iva * w0.y + b0.y;
        o0.z = (x0.z - sm) * iva * w0.z + b0.z;
        o0.w = (x0.w - sm) * iva * w0.w + b0.w;
        o1.x = (x1.x - sm) * iva * w1.x + b1.x;
        o1.y = (x1.y - sm) * iva * w1.y + b1.y;
        o1.z = (x1.z - sm) * iva * w1.z + b1.z;
        o1.w = (x1.w - sm) * iva * w1.w + b1.w;
        __stcs(so + lane,      o0);
        __stcs(so + lane + 32, o1);

        float4 z0, z1, z2;
        z0.x = y0.x * ivm; z0.y = y0.y * ivm; z0.z = y0.z * ivm; z0.w = y0.w * ivm;
        z1.x = y1.x * ivm; z1.y = y1.y * ivm; z1.z = y1.z * ivm; z1.w = y1.w * ivm;
        z2.x = y2.x * ivm; z2.y = y2.y * ivm; z2.z = y2.z * ivm; z2.w = y2.w * ivm;
        __stcs(vo + lane,      z0);
        __stcs(vo + lane + 32, z1);
        __stcs(vo + lane + 64, z2);

        x0 = nx0; x1 = nx1; y0 = ny0; y1 = ny1; y2 = ny2;
        node = nxt;
    }
}

extern "C" void kernel_launch(void* const* d_in, const int* in_sizes, int n_in,
                              void* d_out, int out_size)
{
    const float* s      = (const float*)d_in[0];
    const float* v      = (const float*)d_in[1];
    const float* weight = (const float*)d_in[2];
    const float* bias   = (const float*)d_in[3];
    const int*   batch  = (const int*)d_in[4];

    int n = in_sizes[0] / 256;
    float* sout = (float*)d_out;
    float* vout = (float*)d_out + (size_t)n * 256;

    fused_kernel<<<NSEG, 512>>>(s, v, weight, bias, batch, n, sout, vout);
}

// round 5
// speedup vs baseline: 1.0322x; 1.0322x over previous
#include <cuda_runtime.h>
#include <cuda_bf16.h>

#define NSEG 2048
#define EPS 1e-6f

__device__ __forceinline__ float dot4(float4 a, float4 b) {
    return a.x * b.x + a.y * b.y + a.z * b.z + a.w * b.w;
}
__device__ __forceinline__ float sum4(float4 a) {
    return a.x + a.y + a.z + a.w;
}

// Warp-parallel lower_bound over sorted batch: smallest i with batch[i] >= target.
// 32-ary search: ~4 ballot rounds for n=200000.
__device__ __forceinline__ int warp_lower_bound(const int* __restrict__ batch,
                                                int n, int target, int lane)
{
    int lo = -1, hi = n;   // invariant: batch[lo] < target <= batch[hi] (sentinels)
    while (hi - lo > 1) {
        int span = hi - lo - 1;                       // >= 1
        int pos  = lo + 1 + (int)(((long long)span * lane) >> 5);  // in [lo+1, hi-1]
        int val  = __ldg(batch + pos);
        unsigned ball = __ballot_sync(0xFFFFFFFFu, val >= target);
        if (ball == 0) {
            lo = lo + 1 + (int)(((long long)span * 31) >> 5);
        } else {
            int k0 = __ffs((int)ball) - 1;
            int hi_new = __shfl_sync(0xFFFFFFFFu, pos, k0);
            int lo_new = (k0 > 0) ? __shfl_sync(0xFFFFFFFFu, pos, k0 - 1) : lo;
            hi = hi_new;
            lo = lo_new;
        }
    }
    return hi;
}

// One CTA per segment (batch is sorted -> contiguous node range).
// Pass 1: stats (default .ca loads -> resident in L2). Pass 2: normalize in
// REVERSE order (MRU-first), .cs loads / .cs stores so dead data evicts first.
// min 2 CTAs/SM enforced: occupancy > register tricks for this kernel.
__global__ __launch_bounds__(512, 2) void fused_kernel(
    const float* __restrict__ s, const float* __restrict__ v,
    const float* __restrict__ weight, const float* __restrict__ bias,
    const int* __restrict__ batch, int n,
    float* __restrict__ sout, float* __restrict__ vout)
{
    __shared__ float sh_acc[3];
    __shared__ int   sh_n0, sh_n1;

    int seg  = blockIdx.x;
    int warp = threadIdx.x >> 5;    // 16 warps
    int lane = threadIdx.x & 31;

    if (threadIdx.x < 3) sh_acc[threadIdx.x] = 0.f;
    if (warp == 0) {
        int n0 = warp_lower_bound(batch, n, seg, lane);
        if (lane == 0) sh_n0 = n0;
    } else if (warp == 1) {
        int n1 = warp_lower_bound(batch, n, seg + 1, lane);
        if (lane == 0) sh_n1 = n1;
    }
    __syncthreads();

    int n0 = sh_n0;
    int n1 = sh_n1;
    int cnt = n1 - n0;
    if (cnt == 0) return;           // empty segment: nothing to write

    // ---- pass 1: stats (forward traversal) ----
    float sa = 0.f, sb = 0.f, sw = 0.f;
    for (int node = n0 + warp; node < n1; node += 16) {
        const float4* srow = (const float4*)(s + (size_t)node * 256);
        const float4* vrow = (const float4*)(v + (size_t)node * 384);
        float4 x0 = srow[lane];
        float4 x1 = srow[lane + 32];
        float4 y0 = vrow[lane];
        float4 y1 = vrow[lane + 32];
        float4 y2 = vrow[lane + 64];
        sa += sum4(x0) + sum4(x1);
        sb += dot4(x0, x0) + dot4(x1, x1);
        sw += dot4(y0, y0) + dot4(y1, y1) + dot4(y2, y2);
    }
    #pragma unroll
    for (int o = 16; o > 0; o >>= 1) {
        sa += __shfl_xor_sync(0xFFFFFFFFu, sa, o);
        sb += __shfl_xor_sync(0xFFFFFFFFu, sb, o);
        sw += __shfl_xor_sync(0xFFFFFFFFu, sw, o);
    }
    if (lane == 0) {
        atomicAdd(&sh_acc[0], sa);
        atomicAdd(&sh_acc[1], sb);
        atomicAdd(&sh_acc[2], sw);
    }
    __syncthreads();

    // stats: every thread computes redundantly (saves a barrier)
    float c   = (float)cnt;
    float sm  = sh_acc[0] * (1.f / 256.f) / c;
    float ex2 = sh_acc[1] * (1.f / 256.f) / c;
    float var = fmaxf(ex2 - sm * sm, EPS);
    float vm  = fmaxf(sh_acc[2] * (1.f / 128.f) / c, EPS);
    float iva = __fdividef(1.f, var);
    float ivm = __fdividef(1.f, vm);

    float4 w0 = ((const float4*)weight)[lane];
    float4 w1 = ((const float4*)weight)[lane + 32];
    float4 b0 = ((const float4*)bias)[lane];
    float4 b1 = ((const float4*)bias)[lane + 32];

    // ---- pass 2: normalize (REVERSE traversal, MRU-first; streaming) ----
    for (int node = n1 - 1 - warp; node >= n0; node -= 16) {
        const float4* srow = (const float4*)(s + (size_t)node * 256);
        const float4* vrow = (const float4*)(v + (size_t)node * 384);
        float4*       so   = (float4*)(sout + (size_t)node * 256);
        float4*       vo   = (float4*)(vout + (size_t)node * 384);

        float4 x0 = __ldcs(srow + lane);
        float4 x1 = __ldcs(srow + lane + 32);
        float4 y0 = __ldcs(vrow + lane);
        float4 y1 = __ldcs(vrow + lane + 32);
        float4 y2 = __ldcs(vrow + lane + 64);

        float4 o0, o1;
        o0.x = (x0.x - sm) * iva * w0.x + b0.x;
        o0.y = (x0.y - sm) * iva * w0.y + b0.y;
        o0.z = (x0.z - sm) * iva * w0.z + b0.z;
        o0.w = (x0.w - sm) * iva * w0.w + b0.w;
        o1.x = (x1.x - sm) * iva * w1.x + b1.x;
        o1.y = (x1.y - sm) * iva * w1.y + b1.y;
        o1.z = (x1.z - sm) * iva * w1.z + b1.z;
        o1.w = (x1.w - sm) * iva * w1.w + b1.w;
        __stcs(so + lane,      o0);
        __stcs(so + lane + 32, o1);

        float4 z0, z1, z2;
        z0.x = y0.x * ivm; z0.y = y0.y * ivm; z0.z = y0.z * ivm; z0.w = y0.w * ivm;
        z1.x = y1.x * ivm; z1.y = y1.y * ivm; z1.z = y1.z * ivm; z1.w = y1.w * ivm;
        z2.x = y2.x * ivm; z2.y = y2.y * ivm; z2.z = y2.z * ivm; z2.w = y2.w * ivm;
        __stcs(vo + lane,      z0);
        __stcs(vo + lane + 32, z1);
        __stcs(vo + lane + 64, z2);
    }
}

extern "C" void kernel_launch(void* const* d_in, const int* in_sizes, int n_in,
                              void* d_out, int out_size)
{
    const float* s      = (const float*)d_in[0];
    const float* v      = (const float*)d_in[1];
    const float* weight = (const float*)d_in[2];
    const float* bias   = (const float*)d_in[3];
    const int*   batch  = (const int*)d_in[4];

    int n = in_sizes[0] / 256;
    float* sout = (float*)d_out;
    float* vout = (float*)d_out + (size_t)n * 256;

    fused_kernel<<<NSEG, 512>>>(s, v, weight, bias, batch, n, sout, vout);
}